// round 10
// baseline (speedup 1.0000x reference)
#include <cuda_runtime.h>
#include <cuda_bf16.h>
#include <cstdint>
#include <math.h>

// ---------------- problem constants ----------------
#define Hd   256
#define NHd  4
#define HDd  64
#define BAT  8
#define SQI  2048
#define SQT  1024
#define RI   (BAT*SQI)       // 16384 image rows
#define RT   (BAT*SQT)       // 8192 text rows
#define NRS  (RI*NHd/4 + RT*NHd/4)
#define NPART (2*1024*1024)  // partial rowsums: max(32*2048*32, 32*1024*64) = 2M

// ---------------- scratch ----------------
__device__ float g_im[(size_t)RI*Hd];   // packed image
__device__ float g_tx[(size_t)RT*Hd];   // packed text
__device__ float g_w[8*(size_t)Hd*Hd]; // packed weights: i2t q,k,v,o then t2i q,k,v,o
__device__ float g_qi[(size_t)RI*Hd];
__device__ float g_ki[(size_t)RI*Hd];
__device__ float g_vi[(size_t)RI*Hd];   // packed, TRANSPOSED [B*4+hgrp][64][SQI]
__device__ float g_qt[(size_t)RT*Hd];
__device__ float g_kt[(size_t)RT*Hd];
__device__ float g_vt[(size_t)RT*Hd];
__device__ float g_ai[(size_t)RI*Hd];
__device__ float g_at[(size_t)RT*Hd];
__device__ float g_oi[(size_t)RI*Hd];
__device__ float g_ot[(size_t)RT*Hd];
__device__ float g_S[(size_t)BAT*NHd*SQI*SQT]; // packed w = exp(scores)
__device__ float g_rsum[NRS];
__device__ float g_part[NPART];

// ================= helpers =================
__device__ __forceinline__ uint32_t smem_to_u32(const void* p) {
    uint32_t a;
    asm("{ .reg .u64 t; cvta.to.shared.u64 t, %1; cvt.u32.u64 %0, t; }" : "=r"(a) : "l"(p));
    return a;
}
__device__ __forceinline__ void ldm_x4(uint32_t r[4], uint32_t addr) {
    asm volatile("ldmatrix.sync.aligned.m8n8.x4.shared.b16 {%0,%1,%2,%3}, [%4];"
        : "=r"(r[0]), "=r"(r[1]), "=r"(r[2]), "=r"(r[3]) : "r"(addr));
}
__device__ __forceinline__ void mma_bf16(float c[4], const uint32_t a[4],
                                         uint32_t b0, uint32_t b1) {
    asm volatile(
        "mma.sync.aligned.m16n8k16.row.col.f32.bf16.bf16.f32 "
        "{%0,%1,%2,%3}, {%4,%5,%6,%7}, {%8,%9}, {%0,%1,%2,%3};"
        : "+f"(c[0]), "+f"(c[1]), "+f"(c[2]), "+f"(c[3])
        : "r"(a[0]), "r"(a[1]), "r"(a[2]), "r"(a[3]), "r"(b0), "r"(b1));
}
__device__ __forceinline__ uint32_t pack_f32(float x) {
    __nv_bfloat16 hb = __float2bfloat16(x);
    float hf = __bfloat162float(hb);
    __nv_bfloat16 lb = __float2bfloat16(x - hf);
    return ((uint32_t)__bfloat16_as_ushort(hb) << 16) | (uint32_t)__bfloat16_as_ushort(lb);
}
__device__ __forceinline__ float unpack_f32(uint32_t u) {
    return __bfloat162float(__ushort_as_bfloat16((unsigned short)(u >> 16)))
         + __bfloat162float(__ushort_as_bfloat16((unsigned short)(u & 0xffff)));
}

// ---------------- smem layout ----------------
// row stride 56 halves (112B): 16B aligned, ldmatrix bank-clean (row*28 % 32 distinct)
#define RSTR 56
#define OFF_AL 14336
#define OFF_BH 28672
#define OFF_BL 35840
#define STG_BYTES 43008
#define SMEM_GEMM (2*STG_BYTES)   // 86016

struct GArgs {
    const uint32_t* A; int lda;
    const uint32_t* B; int ldb;
    const float* bias;
    void* C; int ldc;
    int K; float alpha;
    int m0, n0;
    int tr_ld, tr_rows, tr_col0;
    const float* rs;      // OMODE1: per-row scale
    float* part; int nparts;  // OMODE3: deterministic partial rowsums
};

// 8 packed words -> 8 hi halves + 8 lo halves, 2x STS.128
__device__ __forceinline__ void sts8(uint16_t* hi, uint16_t* lo, int idx, uint4 a, uint4 b) {
    uint4 H, L;
    H.x = __byte_perm(a.x, a.y, 0x7632); H.y = __byte_perm(a.z, a.w, 0x7632);
    H.z = __byte_perm(b.x, b.y, 0x7632); H.w = __byte_perm(b.z, b.w, 0x7632);
    L.x = __byte_perm(a.x, a.y, 0x5410); L.y = __byte_perm(a.z, a.w, 0x5410);
    L.z = __byte_perm(b.x, b.y, 0x5410); L.w = __byte_perm(b.z, b.w, 0x5410);
    *(uint4*)(hi + idx) = H;
    *(uint4*)(lo + idx) = L;
}

// OMODE: 0 = fp32 row-major, 1 = packed row-major (optional rowsum scale),
//        2 = packed transposed (Vt), 3 = packed exp + deterministic partial sums
template <int OMODE, bool BIAS>
__device__ void gemm_mma(GArgs g) {
    extern __shared__ char smem[];
    const uint32_t sbase = smem_to_u32(smem);
    const int tid = threadIdx.x;
    const int lane = tid & 31, wid = tid >> 5;
    const int warpM = wid >> 1, warpN = wid & 1;     // 4 x 2 warps

    float c[2][4][4];
#pragma unroll
    for (int i = 0; i < 2; i++)
#pragma unroll
        for (int j = 0; j < 4; j++)
#pragma unroll
            for (int q = 0; q < 4; q++) c[i][j][q] = 0.f;

    const int S = g.K >> 5;                    // K-chunks of 32
    const int arow = tid >> 1, ak0 = (tid & 1) * 16;
    const int brow = tid >> 2, bk0 = (tid & 3) * 8;

    uint4 areg[4], breg[2];

#define LOADR(s) do { \
        const uint32_t* Ap = g.A + (size_t)(g.m0 + arow) * g.lda + (s) * 32 + ak0; \
        _Pragma("unroll") for (int j = 0; j < 4; j++) areg[j] = *(const uint4*)(Ap + j * 4); \
        const uint32_t* Bp = g.B + (size_t)(g.n0 + brow) * g.ldb + (s) * 32 + bk0; \
        _Pragma("unroll") for (int j = 0; j < 2; j++) breg[j] = *(const uint4*)(Bp + j * 4); \
    } while (0)

#define STS(buf) do { \
        char* p = smem + (buf) * STG_BYTES; \
        uint16_t* Ah = (uint16_t*)p;               uint16_t* Al = (uint16_t*)(p + OFF_AL); \
        uint16_t* Bh = (uint16_t*)(p + OFF_BH);    uint16_t* Bl = (uint16_t*)(p + OFF_BL); \
        sts8(Ah, Al, arow * RSTR + ak0,     areg[0], areg[1]); \
        sts8(Ah, Al, arow * RSTR + ak0 + 8, areg[2], areg[3]); \
        sts8(Bh, Bl, brow * RSTR + bk0,     breg[0], breg[1]); \
    } while (0)

    const int sel = lane >> 3, r8 = lane & 7;
    const int rloc = (sel & 1) * 8 + r8;
    const int cloc = (sel >> 1) * 8;

#define COMPUTE(buf) do { \
        uint32_t AhB = sbase + (buf) * STG_BYTES, AlB = AhB + OFF_AL; \
        uint32_t BhB = AhB + OFF_BH,              BlB = AhB + OFF_BL; \
        _Pragma("unroll") for (int kh = 0; kh < 2; kh++) { \
            uint32_t ah[2][4], al[2][4], bh[2][4], bl[2][4]; \
            _Pragma("unroll") for (int i = 0; i < 2; i++) { \
                uint32_t off = (uint32_t)(((warpM * 32 + i * 16 + rloc) * RSTR + kh * 16 + cloc) * 2); \
                ldm_x4(ah[i], AhB + off); ldm_x4(al[i], AlB + off); \
            } \
            _Pragma("unroll") for (int pp = 0; pp < 2; pp++) { \
                uint32_t off = (uint32_t)(((warpN * 32 + pp * 16 + rloc) * RSTR + kh * 16 + cloc) * 2); \
                ldm_x4(bh[pp], BhB + off); ldm_x4(bl[pp], BlB + off); \
            } \
            _Pragma("unroll") for (int i = 0; i < 2; i++) \
            _Pragma("unroll") for (int j = 0; j < 4; j++) { \
                const int pp = j >> 1, q = j & 1; \
                mma_bf16(c[i][j], ah[i], bh[pp][q], bh[pp][q + 2]); \
                mma_bf16(c[i][j], ah[i], bl[pp][q], bl[pp][q + 2]); \
                mma_bf16(c[i][j], al[i], bh[pp][q], bh[pp][q + 2]); \
            } \
        } \
    } while (0)

    LOADR(0); STS(0);
    __syncthreads();
    for (int s = 0; s < S; ++s) {
        if (s + 1 < S) LOADR(s + 1);
        COMPUTE(s & 1);
        if (s + 1 < S) STS((s + 1) & 1);
        __syncthreads();
    }

    // ---------------- epilogue ----------------
    const int gq = lane >> 2, tig = lane & 3;
#pragma unroll
    for (int i = 0; i < 2; i++) {
        const int r0 = g.m0 + warpM * 32 + i * 16 + gq;   // and r0+8
        float inv0 = 1.f, inv1 = 1.f;
        if (OMODE == 1) {
            if (g.rs) { inv0 = 1.f / g.rs[r0]; inv1 = 1.f / g.rs[r0 + 8]; }
        }
        float ps0 = 0.f, ps1 = 0.f;
#pragma unroll
        for (int j = 0; j < 4; j++) {
            const int nc = warpN * 32 + j * 8 + tig * 2;
            float v00 = c[i][j][0] * g.alpha, v01 = c[i][j][1] * g.alpha;
            float v10 = c[i][j][2] * g.alpha, v11 = c[i][j][3] * g.alpha;
            if (BIAS) {
                float b0 = g.bias[g.n0 + nc], b1 = g.bias[g.n0 + nc + 1];
                v00 += b0; v01 += b1; v10 += b0; v11 += b1;
            }
            if (OMODE == 0) {
                float* Cf = (float*)g.C;
                *(float2*)(Cf + (size_t)r0 * g.ldc + g.n0 + nc)       = make_float2(v00, v01);
                *(float2*)(Cf + (size_t)(r0 + 8) * g.ldc + g.n0 + nc) = make_float2(v10, v11);
            } else if (OMODE == 1) {
                v00 *= inv0; v01 *= inv0; v10 *= inv1; v11 *= inv1;
                uint32_t* Cu = (uint32_t*)g.C;
                *(uint2*)(Cu + (size_t)r0 * g.ldc + g.n0 + nc)       = make_uint2(pack_f32(v00), pack_f32(v01));
                *(uint2*)(Cu + (size_t)(r0 + 8) * g.ldc + g.n0 + nc) = make_uint2(pack_f32(v10), pack_f32(v11));
            } else if (OMODE == 2) {
                uint32_t* Ct = (uint32_t*)g.C;
                const int bb0 = r0 / g.tr_rows, sr0 = r0 % g.tr_rows;
                const int bb1 = (r0 + 8) / g.tr_rows, sr1 = (r0 + 8) % g.tr_rows;
                const size_t base0 = (size_t)((bb0 * 4 + g.tr_col0) * 64 + nc) * g.tr_ld + sr0;
                const size_t base1 = (size_t)((bb1 * 4 + g.tr_col0) * 64 + nc) * g.tr_ld + sr1;
                Ct[base0]            = pack_f32(v00);
                Ct[base0 + g.tr_ld]  = pack_f32(v01);
                Ct[base1]            = pack_f32(v10);
                Ct[base1 + g.tr_ld]  = pack_f32(v11);
            } else {                    // OMODE 3: w = exp(score), packed + partial sums
                float w00 = __expf(v00), w01 = __expf(v01);
                float w10 = __expf(v10), w11 = __expf(v11);
                ps0 += w00 + w01; ps1 += w10 + w11;
                uint32_t* Cu = (uint32_t*)g.C;
                *(uint2*)(Cu + (size_t)r0 * g.ldc + g.n0 + nc) =
                    make_uint2(pack_f32(w00), pack_f32(w01));
                *(uint2*)(Cu + (size_t)(r0 + 8) * g.ldc + g.n0 + nc) =
                    make_uint2(pack_f32(w10), pack_f32(w11));
            }
        }
        if (OMODE == 3) {
            // quad reduce (lanes tig 0..3 cover 32 distinct cols of warpN half)
            ps0 += __shfl_xor_sync(0xffffffffu, ps0, 1);
            ps0 += __shfl_xor_sync(0xffffffffu, ps0, 2);
            ps1 += __shfl_xor_sync(0xffffffffu, ps1, 1);
            ps1 += __shfl_xor_sync(0xffffffffu, ps1, 2);
            if (tig == 0) {  // unique slot per (row, 32-col tile): deterministic
                const int pidx = g.n0 / 32 + warpN;
                g.part[(size_t)r0 * g.nparts + pidx]       = ps0;
                g.part[(size_t)(r0 + 8) * g.nparts + pidx] = ps1;
            }
        }
    }
#undef LOADR
#undef STS
#undef COMPUTE
}

// ---------------- kernel wrappers ----------------
__global__ void __launch_bounds__(256) k_proj_pack(const uint32_t* A, const uint32_t* W,
                                                   const float* bias, uint32_t* C) {
    GArgs g;
    g.A = A; g.lda = Hd;
    g.B = W; g.ldb = Hd;
    g.bias = bias; g.C = C; g.ldc = Hd; g.K = Hd; g.alpha = 1.f;
    g.m0 = blockIdx.y * 128; g.n0 = blockIdx.x * 64;
    g.tr_ld = 1; g.tr_rows = 1; g.tr_col0 = 0; g.rs = nullptr; g.part = nullptr; g.nparts = 0;
    gemm_mma<1, true>(g);
}
__global__ void __launch_bounds__(256) k_proj_vt(const uint32_t* A, const uint32_t* W,
                                                 const float* bias, uint32_t* Vt, int Skv) {
    GArgs g;
    g.A = A; g.lda = Hd;
    g.B = W; g.ldb = Hd;
    g.bias = bias; g.C = Vt; g.ldc = Hd; g.K = Hd; g.alpha = 1.f;
    g.m0 = blockIdx.y * 128; g.n0 = blockIdx.x * 64;
    g.tr_ld = Skv; g.tr_rows = Skv; g.tr_col0 = blockIdx.x; g.rs = nullptr; g.part = nullptr; g.nparts = 0;
    gemm_mma<2, true>(g);
}
__global__ void __launch_bounds__(256) k_proj_out(const uint32_t* A, const uint32_t* W,
                                                  const float* bias, float* C) {
    GArgs g;
    g.A = A; g.lda = Hd;
    g.B = W; g.ldb = Hd;
    g.bias = bias; g.C = C; g.ldc = Hd; g.K = Hd; g.alpha = 1.f;
    g.m0 = blockIdx.y * 128; g.n0 = blockIdx.x * 64;
    g.tr_ld = 1; g.tr_rows = 1; g.tr_col0 = 0; g.rs = nullptr; g.part = nullptr; g.nparts = 0;
    gemm_mma<0, true>(g);
}
__global__ void __launch_bounds__(256) k_scores_tc(const uint32_t* Q, const uint32_t* Kt,
                                                   uint32_t* So, float* part, int Sq, int Skv) {
    const int z = blockIdx.z, b = z >> 2, h = z & 3;
    GArgs g;
    g.A = Q + (size_t)b * Sq * Hd + h * HDd; g.lda = Hd;
    g.B = Kt + (size_t)b * Skv * Hd + h * HDd; g.ldb = Hd;
    g.bias = nullptr; g.C = So + (size_t)z * Sq * Skv; g.ldc = Skv;
    g.K = HDd; g.alpha = 2.0f;  // 1/TEMP
    g.m0 = blockIdx.y * 128; g.n0 = blockIdx.x * 64;
    g.tr_ld = 1; g.tr_rows = 1; g.tr_col0 = 0; g.rs = nullptr;
    g.nparts = Skv / 32;
    g.part = part + (size_t)z * Sq * g.nparts;
    gemm_mma<3, false>(g);
}
__global__ void __launch_bounds__(256) k_pv_tc(const uint32_t* P, const uint32_t* Vt,
                                               uint32_t* attn, const float* rsum, int Sq, int Skv) {
    const int z = blockIdx.z, b = z >> 2, h = z & 3;
    GArgs g;
    g.A = P + (size_t)z * Sq * Skv; g.lda = Skv;
    g.B = Vt + (size_t)z * HDd * Skv; g.ldb = Skv;
    g.bias = nullptr; g.C = attn + (size_t)b * Sq * Hd + h * HDd; g.ldc = Hd;
    g.K = Skv; g.alpha = 1.f;
    g.m0 = blockIdx.y * 128; g.n0 = 0;
    g.tr_ld = 1; g.tr_rows = 1; g.tr_col0 = 0;
    g.rs = rsum + (size_t)z * Sq; g.part = nullptr; g.nparts = 0;
    gemm_mma<1, false>(g);
}

// ---------------- prepack fp32 -> hi/lo packed ----------------
__global__ void k_pack(const float* __restrict__ in, uint32_t* __restrict__ out, int n) {
    int i = blockIdx.x * 256 + threadIdx.x;
    if (i < n) out[i] = pack_f32(in[i]);
}

// ---------------- reduce partial rowsums ----------------
__global__ void k_rowsum(const float* __restrict__ part, float* __restrict__ rs,
                         int rows, int nparts) {
    int r = blockIdx.x * 256 + threadIdx.x;
    if (r < rows) {
        const float* p = part + (size_t)r * nparts;
        float s = 0.f;
        for (int i = 0; i < nparts; i++) s += p[i];
        rs[r] = s;
    }
}

// ---------------- head-averaged A (pure streaming, deterministic) ----------------
__global__ void k_avg(const uint32_t* __restrict__ W, const float* __restrict__ rs,
                      float* __restrict__ A, int Sq, int Skv) {
    const int q = blockIdx.x, b = blockIdx.y, t = threadIdx.x;
    const size_t hstride = (size_t)Sq * Skv;
    float inv[4];
#pragma unroll
    for (int h = 0; h < 4; h++) inv[h] = 0.25f / rs[(size_t)(b * 4 + h) * Sq + q];
    const uint32_t* w0 = W + ((size_t)(b * 4) * Sq + q) * (size_t)Skv;
    float* Ar = A + ((size_t)b * Sq + q) * (size_t)Skv;
    for (int k = t; k < Skv; k += 256) {
        float a = 0.f;
#pragma unroll
        for (int h = 0; h < 4; h++)
            a += unpack_f32(w0[(size_t)h * hstride + k]) * inv[h];
        Ar[k] = a;
    }
}

// ---------------- relu + LayerNorm ----------------
__global__ void k_relu_ln(const float* __restrict__ O, const float* __restrict__ gamma,
                          const float* __restrict__ beta, float* __restrict__ out) {
    __shared__ float s1[256], s2[256];
    const int row = blockIdx.x, t = threadIdx.x;
    float x = O[(size_t)row * Hd + t];
    x = fmaxf(x, 0.f);
    s1[t] = x; s2[t] = x * x;
    __syncthreads();
    for (int s = 128; s > 0; s >>= 1) {
        if (t < s) { s1[t] += s1[t + s]; s2[t] += s2[t + s]; }
        __syncthreads();
    }
    const float mean = s1[0] * (1.f / Hd);
    const float var = s2[0] * (1.f / Hd) - mean * mean;
    const float rstd = rsqrtf(var + 1e-5f);
    out[(size_t)row * Hd + t] = (x - mean) * rstd * gamma[t] + beta[t];
}

// ---------------- launch ----------------
extern "C" void kernel_launch(void* const* d_in, const int* in_sizes, int n_in,
                              void* d_out, int out_size) {
    const float* image  = (const float*)d_in[0];
    const float* text   = (const float*)d_in[1];
    const float* i2t_wq = (const float*)d_in[2];
    const float* i2t_bq = (const float*)d_in[3];
    const float* i2t_wk = (const float*)d_in[4];
    const float* i2t_bk = (const float*)d_in[5];
    const float* i2t_wv = (const float*)d_in[6];
    const float* i2t_bv = (const float*)d_in[7];
    const float* i2t_wo = (const float*)d_in[8];
    const float* i2t_bo = (const float*)d_in[9];
    const float* i2t_g  = (const float*)d_in[10];
    const float* i2t_be = (const float*)d_in[11];
    const float* t2i_wq = (const float*)d_in[12];
    const float* t2i_bq = (const float*)d_in[13];
    const float* t2i_wk = (const float*)d_in[14];
    const float* t2i_bk = (const float*)d_in[15];
    const float* t2i_wv = (const float*)d_in[16];
    const float* t2i_bv = (const float*)d_in[17];
    const float* t2i_wo = (const float*)d_in[18];
    const float* t2i_bo = (const float*)d_in[19];
    const float* t2i_g  = (const float*)d_in[20];
    const float* t2i_be = (const float*)d_in[21];

    float* out = (float*)d_out;
    float* out_i2t_feat = out;
    float* out_t2i_feat = out + (size_t)RI * Hd;
    float* out_i2t_A    = out_t2i_feat + (size_t)RT * Hd;
    float* out_t2i_A    = out_i2t_A + (size_t)BAT * SQI * SQT;

    float *im, *tx, *w, *qi, *ki, *vi, *qt, *kt, *vt, *ai, *at, *oi, *ot, *S, *rsum, *part;
    cudaGetSymbolAddress((void**)&im, g_im);
    cudaGetSymbolAddress((void**)&tx, g_tx);
    cudaGetSymbolAddress((void**)&w,  g_w);
    cudaGetSymbolAddress((void**)&qi, g_qi);
    cudaGetSymbolAddress((void**)&ki, g_ki);
    cudaGetSymbolAddress((void**)&vi, g_vi);
    cudaGetSymbolAddress((void**)&qt, g_qt);
    cudaGetSymbolAddress((void**)&kt, g_kt);
    cudaGetSymbolAddress((void**)&vt, g_vt);
    cudaGetSymbolAddress((void**)&ai, g_ai);
    cudaGetSymbolAddress((void**)&at, g_at);
    cudaGetSymbolAddress((void**)&oi, g_oi);
    cudaGetSymbolAddress((void**)&ot, g_ot);
    cudaGetSymbolAddress((void**)&S,  g_S);
    cudaGetSymbolAddress((void**)&rsum, g_rsum);
    cudaGetSymbolAddress((void**)&part, g_part);
    float* rsA = rsum;
    float* rsB = rsum + (size_t)BAT * NHd * SQI;
    uint32_t* wp = (uint32_t*)w;
    uint32_t* w_i2t_q = wp;                 uint32_t* w_i2t_k = wp + 1 * Hd * Hd;
    uint32_t* w_i2t_v = wp + 2 * Hd * Hd;   uint32_t* w_i2t_o = wp + 3 * Hd * Hd;
    uint32_t* w_t2i_q = wp + 4 * Hd * Hd;   uint32_t* w_t2i_k = wp + 5 * Hd * Hd;
    uint32_t* w_t2i_v = wp + 6 * Hd * Hd;   uint32_t* w_t2i_o = wp + 7 * Hd * Hd;

    cudaFuncSetAttribute(k_proj_pack, cudaFuncAttributeMaxDynamicSharedMemorySize, SMEM_GEMM);
    cudaFuncSetAttribute(k_proj_vt,   cudaFuncAttributeMaxDynamicSharedMemorySize, SMEM_GEMM);
    cudaFuncSetAttribute(k_proj_out,  cudaFuncAttributeMaxDynamicSharedMemorySize, SMEM_GEMM);
    cudaFuncSetAttribute(k_scores_tc, cudaFuncAttributeMaxDynamicSharedMemorySize, SMEM_GEMM);
    cudaFuncSetAttribute(k_pv_tc,     cudaFuncAttributeMaxDynamicSharedMemorySize, SMEM_GEMM);

    const dim3 blk(256);
    const int WN = Hd * Hd;

    // ---- prepack all fp32 operands to hi/lo packed ----
    k_pack<<<(RI * Hd + 255) / 256, blk>>>(image, (uint32_t*)im, RI * Hd);
    k_pack<<<(RT * Hd + 255) / 256, blk>>>(text,  (uint32_t*)tx, RT * Hd);
    k_pack<<<(WN + 255) / 256, blk>>>(i2t_wq, w_i2t_q, WN);
    k_pack<<<(WN + 255) / 256, blk>>>(i2t_wk, w_i2t_k, WN);
    k_pack<<<(WN + 255) / 256, blk>>>(i2t_wv, w_i2t_v, WN);
    k_pack<<<(WN + 255) / 256, blk>>>(i2t_wo, w_i2t_o, WN);
    k_pack<<<(WN + 255) / 256, blk>>>(t2i_wq, w_t2i_q, WN);
    k_pack<<<(WN + 255) / 256, blk>>>(t2i_wk, w_t2i_k, WN);
    k_pack<<<(WN + 255) / 256, blk>>>(t2i_wv, w_t2i_v, WN);
    k_pack<<<(WN + 255) / 256, blk>>>(t2i_wo, w_t2i_o, WN);

    // ---- projections ----
    k_proj_pack<<<dim3(4, RI / 128), blk, SMEM_GEMM>>>((uint32_t*)im, w_i2t_q, i2t_bq, (uint32_t*)qi);
    k_proj_pack<<<dim3(4, RT / 128), blk, SMEM_GEMM>>>((uint32_t*)tx, w_i2t_k, i2t_bk, (uint32_t*)kt);
    k_proj_vt  <<<dim3(4, RT / 128), blk, SMEM_GEMM>>>((uint32_t*)tx, w_i2t_v, i2t_bv, (uint32_t*)vt, SQT);
    k_proj_pack<<<dim3(4, RT / 128), blk, SMEM_GEMM>>>((uint32_t*)tx, w_t2i_q, t2i_bq, (uint32_t*)qt);
    k_proj_pack<<<dim3(4, RI / 128), blk, SMEM_GEMM>>>((uint32_t*)im, w_t2i_k, t2i_bk, (uint32_t*)ki);
    k_proj_vt  <<<dim3(4, RI / 128), blk, SMEM_GEMM>>>((uint32_t*)im, w_t2i_v, t2i_bv, (uint32_t*)vi, SQI);

    // ---- i2t ----
    k_scores_tc<<<dim3(SQT / 64, SQI / 128, BAT * NHd), blk, SMEM_GEMM>>>(
        (const uint32_t*)qi, (const uint32_t*)kt, (uint32_t*)S, part, SQI, SQT);
    k_rowsum<<<(BAT * NHd * SQI + 255) / 256, blk>>>(part, rsA, BAT * NHd * SQI, SQT / 32);
    k_avg<<<dim3(SQI, BAT), blk>>>((const uint32_t*)S, rsA, out_i2t_A, SQI, SQT);
    k_pv_tc<<<dim3(1, SQI / 128, BAT * NHd), blk, SMEM_GEMM>>>(
        (const uint32_t*)S, (const uint32_t*)vt, (uint32_t*)ai, rsA, SQI, SQT);
    k_proj_out<<<dim3(4, RI / 128), blk, SMEM_GEMM>>>((const uint32_t*)ai, w_i2t_o, i2t_bo, oi);
    k_relu_ln<<<RI, blk>>>(oi, i2t_g, i2t_be, out_i2t_feat);

    // ---- t2i ----
    k_scores_tc<<<dim3(SQI / 64, SQT / 128, BAT * NHd), blk, SMEM_GEMM>>>(
        (const uint32_t*)qt, (const uint32_t*)ki, (uint32_t*)S, part, SQT, SQI);
    k_rowsum<<<(BAT * NHd * SQT + 255) / 256, blk>>>(part, rsB, BAT * NHd * SQT, SQI / 32);
    k_avg<<<dim3(SQT, BAT), blk>>>((const uint32_t*)S, rsB, out_t2i_A, SQT, SQI);
    k_pv_tc<<<dim3(1, SQT / 128, BAT * NHd), blk, SMEM_GEMM>>>(
        (const uint32_t*)S, (const uint32_t*)vi, (uint32_t*)at, rsB, SQT, SQI);
    k_proj_out<<<dim3(4, RT / 128), blk, SMEM_GEMM>>>((const uint32_t*)at, w_t2i_o, t2i_bo, ot);
    k_relu_ln<<<RT, blk>>>(ot, t2i_g, t2i_be, out_t2i_feat);
}

// round 12
// speedup vs baseline: 1.0022x; 1.0022x over previous
#include <cuda_runtime.h>
#include <cuda_bf16.h>
#include <cstdint>
#include <math.h>

// ---------------- problem constants ----------------
#define Hd   256
#define NHd  4
#define HDd  64
#define BAT  8
#define SQI  2048
#define SQT  1024
#define RI   (BAT*SQI)       // 16384 image rows
#define RT   (BAT*SQT)       // 8192 text rows
#define NZ   (BAT*NHd)       // 32

// ---------------- scratch ----------------
__device__ float g_im[(size_t)RI*Hd];   // packed image
__device__ float g_tx[(size_t)RT*Hd];   // packed text
__device__ float g_w[8*(size_t)Hd*Hd]; // packed weights: i2t q,k,v,o then t2i q,k,v,o
__device__ float g_qi[(size_t)RI*Hd];
__device__ float g_ki[(size_t)RI*Hd];
__device__ float g_vi[(size_t)RI*Hd];   // packed, TRANSPOSED [z][64][SQI]
__device__ float g_qt[(size_t)RT*Hd];
__device__ float g_kt[(size_t)RT*Hd];
__device__ float g_vt[(size_t)RT*Hd];   // packed, TRANSPOSED [z][64][SQT]
__device__ float g_ai[(size_t)RI*Hd];
__device__ float g_at[(size_t)RT*Hd];
__device__ float g_oi[(size_t)RI*Hd];
__device__ float g_ot[(size_t)RT*Hd];
__device__ float g_S0[(size_t)NZ*SQI*SQT]; // i2t packed w
__device__ float g_S1[(size_t)NZ*SQT*SQI]; // t2i packed w
__device__ float g_rsum[NZ*SQI + NZ*SQT];
__device__ float g_part0[(size_t)NZ*SQI*(SQT/32)];
__device__ float g_part1[(size_t)NZ*SQT*(SQI/32)];

// ================= helpers =================
__device__ __forceinline__ uint32_t smem_to_u32(const void* p) {
    uint32_t a;
    asm("{ .reg .u64 t; cvta.to.shared.u64 t, %1; cvt.u32.u64 %0, t; }" : "=r"(a) : "l"(p));
    return a;
}
__device__ __forceinline__ void ldm_x4(uint32_t r[4], uint32_t addr) {
    asm volatile("ldmatrix.sync.aligned.m8n8.x4.shared.b16 {%0,%1,%2,%3}, [%4];"
        : "=r"(r[0]), "=r"(r[1]), "=r"(r[2]), "=r"(r[3]) : "r"(addr));
}
__device__ __forceinline__ void mma_bf16(float c[4], const uint32_t a[4],
                                         uint32_t b0, uint32_t b1) {
    asm volatile(
        "mma.sync.aligned.m16n8k16.row.col.f32.bf16.bf16.f32 "
        "{%0,%1,%2,%3}, {%4,%5,%6,%7}, {%8,%9}, {%0,%1,%2,%3};"
        : "+f"(c[0]), "+f"(c[1]), "+f"(c[2]), "+f"(c[3])
        : "r"(a[0]), "r"(a[1]), "r"(a[2]), "r"(a[3]), "r"(b0), "r"(b1));
}
__device__ __forceinline__ uint32_t pack_f32(float x) {
    __nv_bfloat16 hb = __float2bfloat16(x);
    float hf = __bfloat162float(hb);
    __nv_bfloat16 lb = __float2bfloat16(x - hf);
    return ((uint32_t)__bfloat16_as_ushort(hb) << 16) | (uint32_t)__bfloat16_as_ushort(lb);
}
__device__ __forceinline__ float unpack_f32(uint32_t u) {
    return __bfloat162float(__ushort_as_bfloat16((unsigned short)(u >> 16)))
         + __bfloat162float(__ushort_as_bfloat16((unsigned short)(u & 0xffff)));
}

// ---------------- smem layout ----------------
#define RSTR 56
#define OFF_AL 14336
#define OFF_BH 28672
#define OFF_BL 35840
#define STG_BYTES 43008
#define SMEM_GEMM (2*STG_BYTES)   // 86016

struct GArgs {
    const uint32_t* A; int lda;
    const uint32_t* B; int ldb;
    const float* bias;
    void* C; int ldc;
    int K; float alpha;
    int m0, n0;
    int tr_ld, tr_rows, tr_col0;
    const float* rs;
    float* part; int nparts;
};

__device__ __forceinline__ void sts8(uint16_t* hi, uint16_t* lo, int idx, uint4 a, uint4 b) {
    uint4 H, L;
    H.x = __byte_perm(a.x, a.y, 0x7632); H.y = __byte_perm(a.z, a.w, 0x7632);
    H.z = __byte_perm(b.x, b.y, 0x7632); H.w = __byte_perm(b.z, b.w, 0x7632);
    L.x = __byte_perm(a.x, a.y, 0x5410); L.y = __byte_perm(a.z, a.w, 0x5410);
    L.z = __byte_perm(b.x, b.y, 0x5410); L.w = __byte_perm(b.z, b.w, 0x5410);
    *(uint4*)(hi + idx) = H;
    *(uint4*)(lo + idx) = L;
}

// OMODE: 0 fp32 row-major, 1 packed row-major (opt. rowsum scale),
//        2 packed transposed (Vt), 3 packed exp + partial sums
template <int OMODE, bool BIAS>
__device__ void gemm_mma(GArgs g) {
    extern __shared__ char smem[];
    const uint32_t sbase = smem_to_u32(smem);
    const int tid = threadIdx.x;
    const int lane = tid & 31, wid = tid >> 5;
    const int warpM = wid >> 1, warpN = wid & 1;

    float c[2][4][4];
#pragma unroll
    for (int i = 0; i < 2; i++)
#pragma unroll
        for (int j = 0; j < 4; j++)
#pragma unroll
            for (int q = 0; q < 4; q++) c[i][j][q] = 0.f;

    const int S = g.K >> 5;
    const int arow = tid >> 1, ak0 = (tid & 1) * 16;
    const int brow = tid >> 2, bk0 = (tid & 3) * 8;

    uint4 areg[4], breg[2];

#define LOADR(s) do { \
        const uint32_t* Ap = g.A + (size_t)(g.m0 + arow) * g.lda + (s) * 32 + ak0; \
        _Pragma("unroll") for (int j = 0; j < 4; j++) areg[j] = *(const uint4*)(Ap + j * 4); \
        const uint32_t* Bp = g.B + (size_t)(g.n0 + brow) * g.ldb + (s) * 32 + bk0; \
        _Pragma("unroll") for (int j = 0; j < 2; j++) breg[j] = *(const uint4*)(Bp + j * 4); \
    } while (0)

#define STS(buf) do { \
        char* p = smem + (buf) * STG_BYTES; \
        uint16_t* Ah = (uint16_t*)p;               uint16_t* Al = (uint16_t*)(p + OFF_AL); \
        uint16_t* Bh = (uint16_t*)(p + OFF_BH);    uint16_t* Bl = (uint16_t*)(p + OFF_BL); \
        sts8(Ah, Al, arow * RSTR + ak0,     areg[0], areg[1]); \
        sts8(Ah, Al, arow * RSTR + ak0 + 8, areg[2], areg[3]); \
        sts8(Bh, Bl, brow * RSTR + bk0,     breg[0], breg[1]); \
    } while (0)

    const int sel = lane >> 3, r8 = lane & 7;
    const int rloc = (sel & 1) * 8 + r8;
    const int cloc = (sel >> 1) * 8;

#define COMPUTE(buf) do { \
        uint32_t AhB = sbase + (buf) * STG_BYTES, AlB = AhB + OFF_AL; \
        uint32_t BhB = AhB + OFF_BH,              BlB = AhB + OFF_BL; \
        _Pragma("unroll") for (int kh = 0; kh < 2; kh++) { \
            uint32_t ah[2][4], al[2][4], bh[2][4], bl[2][4]; \
            _Pragma("unroll") for (int i = 0; i < 2; i++) { \
                uint32_t off = (uint32_t)(((warpM * 32 + i * 16 + rloc) * RSTR + kh * 16 + cloc) * 2); \
                ldm_x4(ah[i], AhB + off); ldm_x4(al[i], AlB + off); \
            } \
            _Pragma("unroll") for (int pp = 0; pp < 2; pp++) { \
                uint32_t off = (uint32_t)(((warpN * 32 + pp * 16 + rloc) * RSTR + kh * 16 + cloc) * 2); \
                ldm_x4(bh[pp], BhB + off); ldm_x4(bl[pp], BlB + off); \
            } \
            _Pragma("unroll") for (int i = 0; i < 2; i++) \
            _Pragma("unroll") for (int j = 0; j < 4; j++) { \
                const int pp = j >> 1, q = j & 1; \
                mma_bf16(c[i][j], ah[i], bh[pp][q], bh[pp][q + 2]); \
                mma_bf16(c[i][j], ah[i], bl[pp][q], bl[pp][q + 2]); \
                mma_bf16(c[i][j], al[i], bh[pp][q], bh[pp][q + 2]); \
            } \
        } \
    } while (0)

    LOADR(0); STS(0);
    __syncthreads();
    for (int s = 0; s < S; ++s) {
        if (s + 1 < S) LOADR(s + 1);
        COMPUTE(s & 1);
        if (s + 1 < S) STS((s + 1) & 1);
        __syncthreads();
    }

    const int gq = lane >> 2, tig = lane & 3;
#pragma unroll
    for (int i = 0; i < 2; i++) {
        const int r0 = g.m0 + warpM * 32 + i * 16 + gq;
        float inv0 = 1.f, inv1 = 1.f;
        if (OMODE == 1) {
            if (g.rs) { inv0 = 1.f / g.rs[r0]; inv1 = 1.f / g.rs[r0 + 8]; }
        }
        float ps0 = 0.f, ps1 = 0.f;
#pragma unroll
        for (int j = 0; j < 4; j++) {
            const int nc = warpN * 32 + j * 8 + tig * 2;
            float v00 = c[i][j][0] * g.alpha, v01 = c[i][j][1] * g.alpha;
            float v10 = c[i][j][2] * g.alpha, v11 = c[i][j][3] * g.alpha;
            if (BIAS) {
                float b0 = g.bias[g.n0 + nc], b1 = g.bias[g.n0 + nc + 1];
                v00 += b0; v01 += b1; v10 += b0; v11 += b1;
            }
            if (OMODE == 0) {
                float* Cf = (float*)g.C;
                *(float2*)(Cf + (size_t)r0 * g.ldc + g.n0 + nc)       = make_float2(v00, v01);
                *(float2*)(Cf + (size_t)(r0 + 8) * g.ldc + g.n0 + nc) = make_float2(v10, v11);
            } else if (OMODE == 1) {
                v00 *= inv0; v01 *= inv0; v10 *= inv1; v11 *= inv1;
                uint32_t* Cu = (uint32_t*)g.C;
                *(uint2*)(Cu + (size_t)r0 * g.ldc + g.n0 + nc)       = make_uint2(pack_f32(v00), pack_f32(v01));
                *(uint2*)(Cu + (size_t)(r0 + 8) * g.ldc + g.n0 + nc) = make_uint2(pack_f32(v10), pack_f32(v11));
            } else if (OMODE == 2) {
                uint32_t* Ct = (uint32_t*)g.C;
                const int bb0 = r0 / g.tr_rows, sr0 = r0 % g.tr_rows;
                const int bb1 = (r0 + 8) / g.tr_rows, sr1 = (r0 + 8) % g.tr_rows;
                const size_t base0 = (size_t)((bb0 * 4 + g.tr_col0) * 64 + nc) * g.tr_ld + sr0;
                const size_t base1 = (size_t)((bb1 * 4 + g.tr_col0) * 64 + nc) * g.tr_ld + sr1;
                Ct[base0]            = pack_f32(v00);
                Ct[base0 + g.tr_ld]  = pack_f32(v01);
                Ct[base1]            = pack_f32(v10);
                Ct[base1 + g.tr_ld]  = pack_f32(v11);
            } else {
                float w00 = __expf(v00), w01 = __expf(v01);
                float w10 = __expf(v10), w11 = __expf(v11);
                ps0 += w00 + w01; ps1 += w10 + w11;
                uint32_t* Cu = (uint32_t*)g.C;
                *(uint2*)(Cu + (size_t)r0 * g.ldc + g.n0 + nc) =
                    make_uint2(pack_f32(w00), pack_f32(w01));
                *(uint2*)(Cu + (size_t)(r0 + 8) * g.ldc + g.n0 + nc) =
                    make_uint2(pack_f32(w10), pack_f32(w11));
            }
        }
        if (OMODE == 3) {
            ps0 += __shfl_xor_sync(0xffffffffu, ps0, 1);
            ps0 += __shfl_xor_sync(0xffffffffu, ps0, 2);
            ps1 += __shfl_xor_sync(0xffffffffu, ps1, 1);
            ps1 += __shfl_xor_sync(0xffffffffu, ps1, 2);
            if (tig == 0) {
                const int pidx = g.n0 / 32 + warpN;
                g.part[(size_t)r0 * g.nparts + pidx]       = ps0;
                g.part[(size_t)(r0 + 8) * g.nparts + pidx] = ps1;
            }
        }
    }
#undef LOADR
#undef STS
#undef COMPUTE
}

// ---------------- merged kernels ----------------

// all packing in one launch (branch dispatch, no pointer array)
__global__ void __launch_bounds__(256) k_pack_all(
    const float* im, const float* tx,
    const float* w0, const float* w1, const float* w2, const float* w3,
    const float* w4, const float* w5, const float* w6, const float* w7,
    uint32_t* dim, uint32_t* dtx, uint32_t* dw)
{
    const int NIM = RI * Hd, NTX = RT * Hd, NW = Hd * Hd;
    int i = blockIdx.x * 256 + threadIdx.x;
    if (i >= NIM + NTX + 8 * NW) return;
    if (i < NIM) { dim[i] = pack_f32(im[i]); return; }
    i -= NIM;
    if (i < NTX) { dtx[i] = pack_f32(tx[i]); return; }
    i -= NTX;
    const int wsel = i / NW, wi = i % NW;
    const float* src;
    switch (wsel) {
        case 0: src = w0; break; case 1: src = w1; break;
        case 2: src = w2; break; case 3: src = w3; break;
        case 4: src = w4; break; case 5: src = w5; break;
        case 6: src = w6; break; default: src = w7; break;
    }
    dw[(size_t)wsel * NW + wi] = pack_f32(src[wi]);
}

// all 6 QKV projections in one launch. grid (4, 576)
__global__ void __launch_bounds__(256) k_proj_all(
    const uint32_t* im, const uint32_t* tx, const uint32_t* w,
    const float* i2t_bq, const float* i2t_bk, const float* i2t_bv,
    const float* t2i_bq, const float* t2i_bk, const float* t2i_bv,
    uint32_t* qi, uint32_t* ki, uint32_t* vi,
    uint32_t* qt, uint32_t* kt, uint32_t* vt)
{
    const int WN = Hd * Hd;
    const int y = blockIdx.y;
    GArgs g;
    g.lda = Hd; g.ldb = Hd; g.ldc = Hd; g.K = Hd; g.alpha = 1.f;
    g.n0 = blockIdx.x * 64; g.rs = nullptr; g.part = nullptr; g.nparts = 0;
    g.tr_ld = 1; g.tr_rows = 1; g.tr_col0 = 0;
    bool om2 = false;
    if (y < 128) {                // qi = im @ i2t_wq
        g.A = im; g.B = w + 0 * WN; g.bias = i2t_bq; g.C = qi; g.m0 = y * 128;
    } else if (y < 256) {         // ki = im @ t2i_wk
        g.A = im; g.B = w + 5 * WN; g.bias = t2i_bk; g.C = ki; g.m0 = (y - 128) * 128;
    } else if (y < 384) {         // vi = im @ t2i_wv (transposed out)
        g.A = im; g.B = w + 6 * WN; g.bias = t2i_bv; g.C = vi; g.m0 = (y - 256) * 128;
        g.tr_ld = SQI; g.tr_rows = SQI; g.tr_col0 = blockIdx.x; om2 = true;
    } else if (y < 448) {         // qt = tx @ t2i_wq
        g.A = tx; g.B = w + 4 * WN; g.bias = t2i_bq; g.C = qt; g.m0 = (y - 384) * 128;
    } else if (y < 512) {         // kt = tx @ i2t_wk
        g.A = tx; g.B = w + 1 * WN; g.bias = i2t_bk; g.C = kt; g.m0 = (y - 448) * 128;
    } else {                      // vt = tx @ i2t_wv (transposed out)
        g.A = tx; g.B = w + 2 * WN; g.bias = i2t_bv; g.C = vt; g.m0 = (y - 512) * 128;
        g.tr_ld = SQT; g.tr_rows = SQT; g.tr_col0 = blockIdx.x; om2 = true;
    }
    if (om2) gemm_mma<2, true>(g); else gemm_mma<1, true>(g);
}

// both score passes. grid (256, 64)
__global__ void __launch_bounds__(256) k_scores_all(
    const uint32_t* qi, const uint32_t* kt, const uint32_t* qt, const uint32_t* ki,
    uint32_t* S0, uint32_t* S1, float* part0, float* part1)
{
    const int zall = blockIdx.y, bx = blockIdx.x;
    GArgs g;
    g.bias = nullptr; g.alpha = 2.0f; g.K = HDd;
    g.lda = Hd; g.ldb = Hd;
    g.rs = nullptr;
    g.tr_ld = 1; g.tr_rows = 1; g.tr_col0 = 0;
    if (zall < NZ) {   // i2t
        const int z = zall, b = z >> 2, h = z & 3;
        g.A = qi + (size_t)b * SQI * Hd + h * HDd;
        g.B = kt + (size_t)b * SQT * Hd + h * HDd;
        g.C = S0 + (size_t)z * SQI * SQT; g.ldc = SQT;
        g.m0 = (bx >> 4) * 128; g.n0 = (bx & 15) * 64;
        g.nparts = SQT / 32;
        g.part = part0 + (size_t)z * SQI * g.nparts;
    } else {           // t2i
        const int z = zall - NZ, b = z >> 2, h = z & 3;
        g.A = qt + (size_t)b * SQT * Hd + h * HDd;
        g.B = ki + (size_t)b * SQI * Hd + h * HDd;
        g.C = S1 + (size_t)z * SQT * SQI; g.ldc = SQI;
        g.m0 = (bx >> 5) * 128; g.n0 = (bx & 31) * 64;
        g.nparts = SQI / 32;
        g.part = part1 + (size_t)z * SQT * g.nparts;
    }
    gemm_mma<3, false>(g);
}

// reduce partial rowsums, both dirs
__global__ void k_rowsum_all(const float* part0, const float* part1, float* rsum) {
    int r = blockIdx.x * 256 + threadIdx.x;
    const int R0 = NZ * SQI;
    if (r < R0) {
        const float* p = part0 + (size_t)r * (SQT / 32);
        float s = 0.f;
        for (int i = 0; i < SQT / 32; i++) s += p[i];
        rsum[r] = s;
    } else if (r < R0 + NZ * SQT) {
        const int r2 = r - R0;
        const float* p = part1 + (size_t)r2 * (SQI / 32);
        float s = 0.f;
        for (int i = 0; i < SQI / 32; i++) s += p[i];
        rsum[r] = s;
    }
}

// head-averaged A, both dirs. grid (3072, 8)
__global__ void k_avg_all(const uint32_t* S0, const uint32_t* S1, const float* rsum,
                          float* A0, float* A1)
{
    const int b = blockIdx.y, t = threadIdx.x;
    int q = blockIdx.x;
    const uint32_t* W; const float* rs; float* A; int Sq, Skv;
    if (q < SQI) { W = S0; rs = rsum;            A = A0; Sq = SQI; Skv = SQT; }
    else { q -= SQI; W = S1; rs = rsum + NZ*SQI; A = A1; Sq = SQT; Skv = SQI; }
    const size_t hstride = (size_t)Sq * Skv;
    float inv[4];
#pragma unroll
    for (int h = 0; h < 4; h++) inv[h] = 0.25f / rs[(size_t)(b * 4 + h) * Sq + q];
    const uint32_t* w0 = W + ((size_t)(b * 4) * Sq + q) * (size_t)Skv;
    float* Ar = A + ((size_t)b * Sq + q) * (size_t)Skv;
    for (int k = t; k < Skv; k += 256) {
        float a = 0.f;
#pragma unroll
        for (int h = 0; h < 4; h++)
            a += unpack_f32(w0[(size_t)h * hstride + k]) * inv[h];
        Ar[k] = a;
    }
}

// both PV passes. grid (24, 32)
__global__ void __launch_bounds__(256) k_pv_all(
    const uint32_t* S0, const uint32_t* S1, const uint32_t* vt, const uint32_t* vi,
    const float* rsum, uint32_t* ai, uint32_t* at)
{
    const int z = blockIdx.y, b = z >> 2, h = z & 3;
    const int x = blockIdx.x;
    GArgs g;
    g.bias = nullptr; g.alpha = 1.f; g.n0 = 0; g.ldc = Hd;
    g.tr_ld = 1; g.tr_rows = 1; g.tr_col0 = 0; g.part = nullptr; g.nparts = 0;
    if (x < 16) {      // i2t
        g.A = S0 + (size_t)z * SQI * SQT; g.lda = SQT; g.K = SQT;
        g.B = vt + (size_t)z * HDd * SQT; g.ldb = SQT;
        g.C = ai + (size_t)b * SQI * Hd + h * HDd;
        g.m0 = x * 128;
        g.rs = rsum + (size_t)z * SQI;
    } else {           // t2i
        g.A = S1 + (size_t)z * SQT * SQI; g.lda = SQI; g.K = SQI;
        g.B = vi + (size_t)z * HDd * SQI; g.ldb = SQI;
        g.C = at + (size_t)b * SQT * Hd + h * HDd;
        g.m0 = (x - 16) * 128;
        g.rs = rsum + NZ * SQI + (size_t)z * SQT;
    }
    gemm_mma<1, false>(g);
}

// both O-projections. grid (4, 192)
__global__ void __launch_bounds__(256) k_projout_all(
    const uint32_t* ai, const uint32_t* at, const uint32_t* w,
    const float* i2t_bo, const float* t2i_bo, float* oi, float* ot)
{
    const int WN = Hd * Hd;
    const int y = blockIdx.y;
    GArgs g;
    g.lda = Hd; g.ldb = Hd; g.ldc = Hd; g.K = Hd; g.alpha = 1.f;
    g.n0 = blockIdx.x * 64; g.rs = nullptr; g.part = nullptr; g.nparts = 0;
    g.tr_ld = 1; g.tr_rows = 1; g.tr_col0 = 0;
    if (y < 128) { g.A = ai; g.B = w + 3 * WN; g.bias = i2t_bo; g.C = oi; g.m0 = y * 128; }
    else         { g.A = at; g.B = w + 7 * WN; g.bias = t2i_bo; g.C = ot; g.m0 = (y - 128) * 128; }
    gemm_mma<0, true>(g);
}

// relu + LayerNorm, both dirs. grid RI+RT
__global__ void k_reluln_all(const float* oi, const float* ot,
                             const float* g0, const float* b0f,
                             const float* g1, const float* b1f,
                             float* out0, float* out1)
{
    __shared__ float s1[256], s2[256];
    int row = blockIdx.x;
    const int t = threadIdx.x;
    const float* O; const float* gamma; const float* beta; float* out;
    if (row < RI) { O = oi; gamma = g0; beta = b0f; out = out0; }
    else { row -= RI; O = ot; gamma = g1; beta = b1f; out = out1; }
    float x = O[(size_t)row * Hd + t];
    x = fmaxf(x, 0.f);
    s1[t] = x; s2[t] = x * x;
    __syncthreads();
    for (int s = 128; s > 0; s >>= 1) {
        if (t < s) { s1[t] += s1[t + s]; s2[t] += s2[t + s]; }
        __syncthreads();
    }
    const float mean = s1[0] * (1.f / Hd);
    const float var = s2[0] * (1.f / Hd) - mean * mean;
    const float rstd = rsqrtf(var + 1e-5f);
    out[(size_t)row * Hd + t] = (x - mean) * rstd * gamma[t] + beta[t];
}

// ---------------- launch ----------------
extern "C" void kernel_launch(void* const* d_in, const int* in_sizes, int n_in,
                              void* d_out, int out_size) {
    const float* image  = (const float*)d_in[0];
    const float* text   = (const float*)d_in[1];
    const float* i2t_wq = (const float*)d_in[2];
    const float* i2t_bq = (const float*)d_in[3];
    const float* i2t_wk = (const float*)d_in[4];
    const float* i2t_bk = (const float*)d_in[5];
    const float* i2t_wv = (const float*)d_in[6];
    const float* i2t_bv = (const float*)d_in[7];
    const float* i2t_wo = (const float*)d_in[8];
    const float* i2t_bo = (const float*)d_in[9];
    const float* i2t_g  = (const float*)d_in[10];
    const float* i2t_be = (const float*)d_in[11];
    const float* t2i_wq = (const float*)d_in[12];
    const float* t2i_bq = (const float*)d_in[13];
    const float* t2i_wk = (const float*)d_in[14];
    const float* t2i_bk = (const float*)d_in[15];
    const float* t2i_wv = (const float*)d_in[16];
    const float* t2i_bv = (const float*)d_in[17];
    const float* t2i_wo = (const float*)d_in[18];
    const float* t2i_bo = (const float*)d_in[19];
    const float* t2i_g  = (const float*)d_in[20];
    const float* t2i_be = (const float*)d_in[21];

    float* out = (float*)d_out;
    float* out_i2t_feat = out;
    float* out_t2i_feat = out + (size_t)RI * Hd;
    float* out_i2t_A    = out_t2i_feat + (size_t)RT * Hd;
    float* out_t2i_A    = out_i2t_A + (size_t)BAT * SQI * SQT;

    float *im, *tx, *w, *qi, *ki, *vi, *qt, *kt, *vt, *ai, *at, *oi, *ot;
    float *S0, *S1, *rsum, *part0, *part1;
    cudaGetSymbolAddress((void**)&im, g_im);
    cudaGetSymbolAddress((void**)&tx, g_tx);
    cudaGetSymbolAddress((void**)&w,  g_w);
    cudaGetSymbolAddress((void**)&qi, g_qi);
    cudaGetSymbolAddress((void**)&ki, g_ki);
    cudaGetSymbolAddress((void**)&vi, g_vi);
    cudaGetSymbolAddress((void**)&qt, g_qt);
    cudaGetSymbolAddress((void**)&kt, g_kt);
    cudaGetSymbolAddress((void**)&vt, g_vt);
    cudaGetSymbolAddress((void**)&ai, g_ai);
    cudaGetSymbolAddress((void**)&at, g_at);
    cudaGetSymbolAddress((void**)&oi, g_oi);
    cudaGetSymbolAddress((void**)&ot, g_ot);
    cudaGetSymbolAddress((void**)&S0, g_S0);
    cudaGetSymbolAddress((void**)&S1, g_S1);
    cudaGetSymbolAddress((void**)&rsum, g_rsum);
    cudaGetSymbolAddress((void**)&part0, g_part0);
    cudaGetSymbolAddress((void**)&part1, g_part1);

    cudaFuncSetAttribute(k_proj_all,    cudaFuncAttributeMaxDynamicSharedMemorySize, SMEM_GEMM);
    cudaFuncSetAttribute(k_scores_all,  cudaFuncAttributeMaxDynamicSharedMemorySize, SMEM_GEMM);
    cudaFuncSetAttribute(k_pv_all,      cudaFuncAttributeMaxDynamicSharedMemorySize, SMEM_GEMM);
    cudaFuncSetAttribute(k_projout_all, cudaFuncAttributeMaxDynamicSharedMemorySize, SMEM_GEMM);

    const dim3 blk(256);
    const int NPACK = RI * Hd + RT * Hd + 8 * Hd * Hd;

    k_pack_all<<<(NPACK + 255) / 256, blk>>>(
        image, text, i2t_wq, i2t_wk, i2t_wv, i2t_wo, t2i_wq, t2i_wk, t2i_wv, t2i_wo,
        (uint32_t*)im, (uint32_t*)tx, (uint32_t*)w);

    k_proj_all<<<dim3(4, 576), blk, SMEM_GEMM>>>(
        (uint32_t*)im, (uint32_t*)tx, (uint32_t*)w,
        i2t_bq, i2t_bk, i2t_bv, t2i_bq, t2i_bk, t2i_bv,
        (uint32_t*)qi, (uint32_t*)ki, (uint32_t*)vi,
        (uint32_t*)qt, (uint32_t*)kt, (uint32_t*)vt);

    k_scores_all<<<dim3(256, 64), blk, SMEM_GEMM>>>(
        (uint32_t*)qi, (uint32_t*)kt, (uint32_t*)qt, (uint32_t*)ki,
        (uint32_t*)S0, (uint32_t*)S1, part0, part1);

    k_rowsum_all<<<(NZ * SQI + NZ * SQT + 255) / 256, blk>>>(part0, part1, rsum);

    k_avg_all<<<dim3(SQI + SQT, BAT), blk>>>(
        (uint32_t*)S0, (uint32_t*)S1, rsum, out_i2t_A, out_t2i_A);

    k_pv_all<<<dim3(24, 32), blk, SMEM_GEMM>>>(
        (uint32_t*)S0, (uint32_t*)S1, (uint32_t*)vt, (uint32_t*)vi,
        rsum, (uint32_t*)ai, (uint32_t*)at);

    k_projout_all<<<dim3(4, 192), blk, SMEM_GEMM>>>(
        (uint32_t*)ai, (uint32_t*)at, (uint32_t*)w, i2t_bo, t2i_bo, oi, ot);

    k_reluln_all<<<RI + RT, blk>>>(oi, ot, i2t_g, i2t_be, t2i_g, t2i_be,
                                   out_i2t_feat, out_t2i_feat);
}

// round 13
// speedup vs baseline: 1.2578x; 1.2550x over previous
#include <cuda_runtime.h>
#include <cuda_bf16.h>
#include <cstdint>
#include <math.h>

// ---------------- problem constants ----------------
#define Hd   256
#define NHd  4
#define HDd  64
#define BAT  8
#define SQI  2048
#define SQT  1024
#define RI   (BAT*SQI)
#define RT   (BAT*SQT)
#define NZ   (BAT*NHd)       // 32

// ---------------- scratch ----------------
__device__ float g_im[(size_t)RI*Hd];
__device__ float g_tx[(size_t)RT*Hd];
__device__ float g_w[8*(size_t)Hd*Hd];
__device__ float g_qi[(size_t)RI*Hd];
__device__ float g_ki[(size_t)RI*Hd];
__device__ float g_vi[(size_t)RI*Hd];   // packed, TRANSPOSED [z][64][SQI]
__device__ float g_qt[(size_t)RT*Hd];
__device__ float g_kt[(size_t)RT*Hd];
__device__ float g_vt[(size_t)RT*Hd];   // packed, TRANSPOSED [z][64][SQT]
__device__ float g_ai[(size_t)RI*Hd];
__device__ float g_at[(size_t)RT*Hd];
__device__ float g_oi[(size_t)RI*Hd];
__device__ float g_ot[(size_t)RT*Hd];
__device__ float g_S0[(size_t)NZ*SQI*SQT]; // i2t packed w (for A output)
__device__ float g_S1[(size_t)NZ*SQT*SQI]; // t2i packed w
__device__ float g_rsum[NZ*SQI + NZ*SQT];

// ================= helpers =================
__device__ __forceinline__ uint32_t smem_to_u32(const void* p) {
    uint32_t a;
    asm("{ .reg .u64 t; cvta.to.shared.u64 t, %1; cvt.u32.u64 %0, t; }" : "=r"(a) : "l"(p));
    return a;
}
__device__ __forceinline__ void ldm_x4(uint32_t r[4], uint32_t addr) {
    asm volatile("ldmatrix.sync.aligned.m8n8.x4.shared.b16 {%0,%1,%2,%3}, [%4];"
        : "=r"(r[0]), "=r"(r[1]), "=r"(r[2]), "=r"(r[3]) : "r"(addr));
}
__device__ __forceinline__ void mma_bf16(float c[4], const uint32_t a[4],
                                         uint32_t b0, uint32_t b1) {
    asm volatile(
        "mma.sync.aligned.m16n8k16.row.col.f32.bf16.bf16.f32 "
        "{%0,%1,%2,%3}, {%4,%5,%6,%7}, {%8,%9}, {%0,%1,%2,%3};"
        : "+f"(c[0]), "+f"(c[1]), "+f"(c[2]), "+f"(c[3])
        : "r"(a[0]), "r"(a[1]), "r"(a[2]), "r"(a[3]), "r"(b0), "r"(b1));
}
__device__ __forceinline__ uint32_t pack_f32(float x) {
    __nv_bfloat16 hb = __float2bfloat16(x);
    float hf = __bfloat162float(hb);
    __nv_bfloat16 lb = __float2bfloat16(x - hf);
    return ((uint32_t)__bfloat16_as_ushort(hb) << 16) | (uint32_t)__bfloat16_as_ushort(lb);
}
__device__ __forceinline__ float unpack_f32(uint32_t u) {
    return __bfloat162float(__ushort_as_bfloat16((unsigned short)(u >> 16)))
         + __bfloat162float(__ushort_as_bfloat16((unsigned short)(u & 0xffff)));
}
// two fp32 -> bf16x2 hi plane + bf16x2 lo(residual) plane; low half = first elem
__device__ __forceinline__ void split2(float a, float b, uint32_t& h, uint32_t& l) {
    __nv_bfloat16 ah = __float2bfloat16(a), bh = __float2bfloat16(b);
    __nv_bfloat16 al = __float2bfloat16(a - __bfloat162float(ah));
    __nv_bfloat16 bl = __float2bfloat16(b - __bfloat162float(bh));
    h = ((uint32_t)__bfloat16_as_ushort(bh) << 16) | (uint32_t)__bfloat16_as_ushort(ah);
    l = ((uint32_t)__bfloat16_as_ushort(bl) << 16) | (uint32_t)__bfloat16_as_ushort(al);
}

// ---------------- GEMM smem layout (projections) ----------------
#define RSTR 56
#define OFF_AL 14336
#define OFF_BH 28672
#define OFF_BL 35840
#define STG_BYTES 43008
#define SMEM_GEMM (2*STG_BYTES)

struct GArgs {
    const uint32_t* A; int lda;
    const uint32_t* B; int ldb;
    const float* bias;
    void* C; int ldc;
    int K; float alpha;
    int m0, n0;
    int tr_ld, tr_rows, tr_col0;
    const float* rs;
};

__device__ __forceinline__ void sts8(uint16_t* hi, uint16_t* lo, int idx, uint4 a, uint4 b) {
    uint4 H, L;
    H.x = __byte_perm(a.x, a.y, 0x7632); H.y = __byte_perm(a.z, a.w, 0x7632);
    H.z = __byte_perm(b.x, b.y, 0x7632); H.w = __byte_perm(b.z, b.w, 0x7632);
    L.x = __byte_perm(a.x, a.y, 0x5410); L.y = __byte_perm(a.z, a.w, 0x5410);
    L.z = __byte_perm(b.x, b.y, 0x5410); L.w = __byte_perm(b.z, b.w, 0x5410);
    *(uint4*)(hi + idx) = H;
    *(uint4*)(lo + idx) = L;
}

// OMODE: 0 fp32 row-major, 1 packed row-major (opt rowsum scale), 2 packed transposed
template <int OMODE, bool BIAS>
__device__ void gemm_mma(GArgs g) {
    extern __shared__ char smem[];
    const uint32_t sbase = smem_to_u32(smem);
    const int tid = threadIdx.x;
    const int lane = tid & 31, wid = tid >> 5;
    const int warpM = wid >> 1, warpN = wid & 1;

    float c[2][4][4];
#pragma unroll
    for (int i = 0; i < 2; i++)
#pragma unroll
        for (int j = 0; j < 4; j++)
#pragma unroll
            for (int q = 0; q < 4; q++) c[i][j][q] = 0.f;

    const int S = g.K >> 5;
    const int arow = tid >> 1, ak0 = (tid & 1) * 16;
    const int brow = tid >> 2, bk0 = (tid & 3) * 8;
    uint4 areg[4], breg[2];

#define LOADR(s) do { \
        const uint32_t* Ap = g.A + (size_t)(g.m0 + arow) * g.lda + (s) * 32 + ak0; \
        _Pragma("unroll") for (int j = 0; j < 4; j++) areg[j] = *(const uint4*)(Ap + j * 4); \
        const uint32_t* Bp = g.B + (size_t)(g.n0 + brow) * g.ldb + (s) * 32 + bk0; \
        _Pragma("unroll") for (int j = 0; j < 2; j++) breg[j] = *(const uint4*)(Bp + j * 4); \
    } while (0)

#define STS(buf) do { \
        char* p = smem + (buf) * STG_BYTES; \
        uint16_t* Ah = (uint16_t*)p;               uint16_t* Al = (uint16_t*)(p + OFF_AL); \
        uint16_t* Bh = (uint16_t*)(p + OFF_BH);    uint16_t* Bl = (uint16_t*)(p + OFF_BL); \
        sts8(Ah, Al, arow * RSTR + ak0,     areg[0], areg[1]); \
        sts8(Ah, Al, arow * RSTR + ak0 + 8, areg[2], areg[3]); \
        sts8(Bh, Bl, brow * RSTR + bk0,     breg[0], breg[1]); \
    } while (0)

    const int sel = lane >> 3, r8 = lane & 7;
    const int rloc = (sel & 1) * 8 + r8;
    const int cloc = (sel >> 1) * 8;

#define COMPUTE(buf) do { \
        uint32_t AhB = sbase + (buf) * STG_BYTES, AlB = AhB + OFF_AL; \
        uint32_t BhB = AhB + OFF_BH,              BlB = AhB + OFF_BL; \
        _Pragma("unroll") for (int kh = 0; kh < 2; kh++) { \
            uint32_t ah[2][4], al[2][4], bh[2][4], bl[2][4]; \
            _Pragma("unroll") for (int i = 0; i < 2; i++) { \
                uint32_t off = (uint32_t)(((warpM * 32 + i * 16 + rloc) * RSTR + kh * 16 + cloc) * 2); \
                ldm_x4(ah[i], AhB + off); ldm_x4(al[i], AlB + off); \
            } \
            _Pragma("unroll") for (int pp = 0; pp < 2; pp++) { \
                uint32_t off = (uint32_t)(((warpN * 32 + pp * 16 + rloc) * RSTR + kh * 16 + cloc) * 2); \
                ldm_x4(bh[pp], BhB + off); ldm_x4(bl[pp], BlB + off); \
            } \
            _Pragma("unroll") for (int i = 0; i < 2; i++) \
            _Pragma("unroll") for (int j = 0; j < 4; j++) { \
                const int pp = j >> 1, q = j & 1; \
                mma_bf16(c[i][j], ah[i], bh[pp][q], bh[pp][q + 2]); \
                mma_bf16(c[i][j], ah[i], bl[pp][q], bl[pp][q + 2]); \
                mma_bf16(c[i][j], al[i], bh[pp][q], bh[pp][q + 2]); \
            } \
        } \
    } while (0)

    LOADR(0); STS(0);
    __syncthreads();
    for (int s = 0; s < S; ++s) {
        if (s + 1 < S) LOADR(s + 1);
        COMPUTE(s & 1);
        if (s + 1 < S) STS((s + 1) & 1);
        __syncthreads();
    }

    const int gq = lane >> 2, tig = lane & 3;
#pragma unroll
    for (int i = 0; i < 2; i++) {
        const int r0 = g.m0 + warpM * 32 + i * 16 + gq;
        float inv0 = 1.f, inv1 = 1.f;
        if (OMODE == 1) {
            if (g.rs) { inv0 = 1.f / g.rs[r0]; inv1 = 1.f / g.rs[r0 + 8]; }
        }
#pragma unroll
        for (int j = 0; j < 4; j++) {
            const int nc = warpN * 32 + j * 8 + tig * 2;
            float v00 = c[i][j][0] * g.alpha, v01 = c[i][j][1] * g.alpha;
            float v10 = c[i][j][2] * g.alpha, v11 = c[i][j][3] * g.alpha;
            if (BIAS) {
                float b0 = g.bias[g.n0 + nc], b1 = g.bias[g.n0 + nc + 1];
                v00 += b0; v01 += b1; v10 += b0; v11 += b1;
            }
            if (OMODE == 0) {
                float* Cf = (float*)g.C;
                *(float2*)(Cf + (size_t)r0 * g.ldc + g.n0 + nc)       = make_float2(v00, v01);
                *(float2*)(Cf + (size_t)(r0 + 8) * g.ldc + g.n0 + nc) = make_float2(v10, v11);
            } else if (OMODE == 1) {
                v00 *= inv0; v01 *= inv0; v10 *= inv1; v11 *= inv1;
                uint32_t* Cu = (uint32_t*)g.C;
                *(uint2*)(Cu + (size_t)r0 * g.ldc + g.n0 + nc)       = make_uint2(pack_f32(v00), pack_f32(v01));
                *(uint2*)(Cu + (size_t)(r0 + 8) * g.ldc + g.n0 + nc) = make_uint2(pack_f32(v10), pack_f32(v11));
            } else {
                uint32_t* Ct = (uint32_t*)g.C;
                const int bb0 = r0 / g.tr_rows, sr0 = r0 % g.tr_rows;
                const int bb1 = (r0 + 8) / g.tr_rows, sr1 = (r0 + 8) % g.tr_rows;
                const size_t base0 = (size_t)((bb0 * 4 + g.tr_col0) * 64 + nc) * g.tr_ld + sr0;
                const size_t base1 = (size_t)((bb1 * 4 + g.tr_col0) * 64 + nc) * g.tr_ld + sr1;
                Ct[base0]            = pack_f32(v00);
                Ct[base0 + g.tr_ld]  = pack_f32(v01);
                Ct[base1]            = pack_f32(v10);
                Ct[base1 + g.tr_ld]  = pack_f32(v11);
            }
        }
    }
#undef LOADR
#undef STS
#undef COMPUTE
}

// ---------------- fused attention kernel ----------------
// Block = 256 thr = 8 warps x 16 q-rows. Per (z, 128-row q-tile): loop 64-wide kv
// tiles: S = 2*Q.K (MMA), w = exp(S) -> store packed w to S-global, accumulate
// rowsums in regs, P-frags from C-frags (register identity), O += P.V (MMA).
// End: O *= 1/rs (packed out), write rs.
#define DSTR 72                          // smem row stride in halves (144B)
#define ATT_SQH 0
#define ATT_SQL 18432
#define ATT_BUF 36864                    // per-buffer: K hi,lo + V hi,lo
#define ATT_KH  0
#define ATT_KL  9216
#define ATT_VH  18432
#define ATT_VL  27648
#define ATT_BUFSZ 36864
#define SMEM_ATT (ATT_BUF + 2*ATT_BUFSZ) // 110592

__global__ void __launch_bounds__(256) k_attn_all(
    const uint32_t* qi, const uint32_t* kt, const uint32_t* qt, const uint32_t* ki,
    const uint32_t* vt, const uint32_t* vi,
    uint32_t* S0, uint32_t* S1, float* rsum,
    uint32_t* ai, uint32_t* at)
{
    extern __shared__ char smem[];
    const uint32_t sb = smem_to_u32(smem);
    const int tid = threadIdx.x;
    const int lane = tid & 31, wid = tid >> 5;
    const int z = blockIdx.y, b = z >> 2, h = z & 3;
    const int x = blockIdx.x;

    const uint32_t *Q, *Km, *V;
    uint32_t *Sg, *O;
    float* rsg;
    int m0, Skv;
    if (x < 8) {          // t2i (longer blocks first)
        Q = qt + (size_t)b * SQT * Hd + h * HDd;
        Km = ki + (size_t)b * SQI * Hd + h * HDd;
        V = vi + (size_t)z * HDd * SQI;
        Sg = S1 + (size_t)z * SQT * SQI;
        O = at + (size_t)b * SQT * Hd + h * HDd;
        rsg = rsum + NZ * SQI + (size_t)z * SQT;
        m0 = x * 128; Skv = SQI;
    } else {              // i2t
        Q = qi + (size_t)b * SQI * Hd + h * HDd;
        Km = kt + (size_t)b * SQT * Hd + h * HDd;
        V = vt + (size_t)z * HDd * SQT;
        Sg = S0 + (size_t)z * SQI * SQT;
        O = ai + (size_t)b * SQI * Hd + h * HDd;
        rsg = rsum + (size_t)z * SQI;
        m0 = (x - 8) * 128; Skv = SQT;
    }
    const int nsteps = Skv >> 6;

    // ---- stage Q (once) ----
    {
        const int qrow = tid >> 1, qoff = (tid & 1) * 32;
        const uint32_t* Qp = Q + (size_t)(m0 + qrow) * Hd + qoff;
        uint4 qv[8];
#pragma unroll
        for (int j = 0; j < 8; j++) qv[j] = *(const uint4*)(Qp + 4 * j);
        uint16_t* Qh = (uint16_t*)(smem + ATT_SQH);
        uint16_t* Ql = (uint16_t*)(smem + ATT_SQL);
#pragma unroll
        for (int j = 0; j < 4; j++)
            sts8(Qh, Ql, qrow * DSTR + qoff + 8 * j, qv[2 * j], qv[2 * j + 1]);
    }

    // ---- K/V staging helpers ----
    const int krow = tid >> 2, koff = (tid & 3) * 16;
    uint4 kreg[4], vreg[4];
#define ATT_LOAD(s) do { \
        const uint32_t* Kp = Km + (size_t)((s) * 64 + krow) * Hd + koff; \
        _Pragma("unroll") for (int j = 0; j < 4; j++) kreg[j] = *(const uint4*)(Kp + 4 * j); \
        const uint32_t* Vp = V + (size_t)krow * Skv + (s) * 64 + koff; \
        _Pragma("unroll") for (int j = 0; j < 4; j++) vreg[j] = *(const uint4*)(Vp + 4 * j); \
    } while (0)
#define ATT_STS(buf) do { \
        char* p = smem + ATT_BUF + (buf) * ATT_BUFSZ; \
        sts8((uint16_t*)(p + ATT_KH), (uint16_t*)(p + ATT_KL), krow * DSTR + koff,     kreg[0], kreg[1]); \
        sts8((uint16_t*)(p + ATT_KH), (uint16_t*)(p + ATT_KL), krow * DSTR + koff + 8, kreg[2], kreg[3]); \
        sts8((uint16_t*)(p + ATT_VH), (uint16_t*)(p + ATT_VL), krow * DSTR + koff,     vreg[0], vreg[1]); \
        sts8((uint16_t*)(p + ATT_VH), (uint16_t*)(p + ATT_VL), krow * DSTR + koff + 8, vreg[2], vreg[3]); \
    } while (0)

    const int sel = lane >> 3, r8 = lane & 7;
    const int rloc = (sel & 1) * 8 + r8;
    const int cloc = (sel >> 1) * 8;
    const int g = lane >> 2, qd = lane & 3;

    float o[8][4];
#pragma unroll
    for (int nt = 0; nt < 8; nt++)
#pragma unroll
        for (int e = 0; e < 4; e++) o[nt][e] = 0.f;
    float rs0 = 0.f, rs1 = 0.f;

    ATT_LOAD(0); ATT_STS(0);
    __syncthreads();

    for (int s = 0; s < nsteps; ++s) {
        const int buf = s & 1;
        if (s + 1 < nsteps) ATT_LOAD(s + 1);

        const uint32_t bufb = sb + ATT_BUF + buf * ATT_BUFSZ;
        // ---- S tile = Q.K^T (K=64 -> 4 k-frags) ----
        float c[8][4];
#pragma unroll
        for (int nt = 0; nt < 8; nt++)
#pragma unroll
            for (int e = 0; e < 4; e++) c[nt][e] = 0.f;
#pragma unroll
        for (int kf = 0; kf < 4; kf++) {
            uint32_t qh[4], ql[4];
            const uint32_t qoffs = (uint32_t)(((16 * wid + rloc) * DSTR + kf * 16 + cloc) * 2);
            ldm_x4(qh, sb + ATT_SQH + qoffs);
            ldm_x4(ql, sb + ATT_SQL + qoffs);
#pragma unroll
            for (int pp = 0; pp < 4; pp++) {
                uint32_t kh[4], kl[4];
                const uint32_t koffs = (uint32_t)(((pp * 16 + rloc) * DSTR + kf * 16 + cloc) * 2);
                ldm_x4(kh, bufb + ATT_KH + koffs);
                ldm_x4(kl, bufb + ATT_KL + koffs);
#pragma unroll
                for (int q = 0; q < 2; q++) {
                    const int nt = pp * 2 + q;
                    mma_bf16(c[nt], qh, kh[q], kh[q + 2]);
                    mma_bf16(c[nt], qh, kl[q], kl[q + 2]);
                    mma_bf16(c[nt], ql, kh[q], kh[q + 2]);
                }
            }
        }
        // ---- exp, store w, rowsum ----
        const int kv0 = s * 64;
        const int row0 = m0 + 16 * wid + g;
        float w[8][4];
#pragma unroll
        for (int nt = 0; nt < 8; nt++) {
            w[nt][0] = __expf(2.0f * c[nt][0]);
            w[nt][1] = __expf(2.0f * c[nt][1]);
            w[nt][2] = __expf(2.0f * c[nt][2]);
            w[nt][3] = __expf(2.0f * c[nt][3]);
            rs0 += w[nt][0] + w[nt][1];
            rs1 += w[nt][2] + w[nt][3];
            const int col = kv0 + nt * 8 + 2 * qd;
            *(uint2*)&Sg[(size_t)row0 * Skv + col] =
                make_uint2(pack_f32(w[nt][0]), pack_f32(w[nt][1]));
            *(uint2*)&Sg[(size_t)(row0 + 8) * Skv + col] =
                make_uint2(pack_f32(w[nt][2]), pack_f32(w[nt][3]));
        }
        // ---- P frags from C frags (register identity) ----
        uint32_t ph[4][4], pl[4][4];
#pragma unroll
        for (int kf = 0; kf < 4; kf++) {
            const int n0 = 2 * kf, n1 = n0 + 1;
            split2(w[n0][0], w[n0][1], ph[kf][0], pl[kf][0]);
            split2(w[n0][2], w[n0][3], ph[kf][1], pl[kf][1]);
            split2(w[n1][0], w[n1][1], ph[kf][2], pl[kf][2]);
            split2(w[n1][2], w[n1][3], ph[kf][3], pl[kf][3]);
        }
        // ---- O += P.V ----
#pragma unroll
        for (int kf = 0; kf < 4; kf++) {
#pragma unroll
            for (int pp = 0; pp < 4; pp++) {
                uint32_t vh[4], vl[4];
                const uint32_t voffs = (uint32_t)(((pp * 16 + rloc) * DSTR + kf * 16 + cloc) * 2);
                ldm_x4(vh, bufb + ATT_VH + voffs);
                ldm_x4(vl, bufb + ATT_VL + voffs);
#pragma unroll
                for (int q = 0; q < 2; q++) {
                    const int nt = pp * 2 + q;
                    mma_bf16(o[nt], ph[kf], vh[q], vh[q + 2]);
                    mma_bf16(o[nt], ph[kf], vl[q], vl[q + 2]);
                    mma_bf16(o[nt], pl[kf], vh[q], vh[q + 2]);
                }
            }
        }
        if (s + 1 < nsteps) ATT_STS((s + 1) & 1);
        __syncthreads();
    }

    // ---- epilogue: rowsums + normalized packed O ----
    rs0 += __shfl_xor_sync(0xffffffffu, rs0, 1);
    rs0 += __shfl_xor_sync(0xffffffffu, rs0, 2);
    rs1 += __shfl_xor_sync(0xffffffffu, rs1, 1);
    rs1 += __shfl_xor_sync(0xffffffffu, rs1, 2);
    const int row0 = m0 + 16 * wid + g;
    if (qd == 0) {
        rsg[row0] = rs0;
        rsg[row0 + 8] = rs1;
    }
    const float inv0 = 1.f / rs0, inv1 = 1.f / rs1;
#pragma unroll
    for (int nt = 0; nt < 8; nt++) {
        const int col = nt * 8 + 2 * qd;
        *(uint2*)&O[(size_t)row0 * Hd + col] =
            make_uint2(pack_f32(o[nt][0] * inv0), pack_f32(o[nt][1] * inv0));
        *(uint2*)&O[(size_t)(row0 + 8) * Hd + col] =
            make_uint2(pack_f32(o[nt][2] * inv1), pack_f32(o[nt][3] * inv1));
    }
#undef ATT_LOAD
#undef ATT_STS
}

// ---------------- other kernels ----------------
__global__ void __launch_bounds__(256) k_pack_all(
    const float* im, const float* tx,
    const float* w0, const float* w1, const float* w2, const float* w3,
    const float* w4, const float* w5, const float* w6, const float* w7,
    uint32_t* dim, uint32_t* dtx, uint32_t* dw)
{
    const int NIM = RI * Hd, NTX = RT * Hd, NW = Hd * Hd;
    int i = blockIdx.x * 256 + threadIdx.x;
    if (i >= NIM + NTX + 8 * NW) return;
    if (i < NIM) { dim[i] = pack_f32(im[i]); return; }
    i -= NIM;
    if (i < NTX) { dtx[i] = pack_f32(tx[i]); return; }
    i -= NTX;
    const int wsel = i / NW, wi = i % NW;
    const float* src;
    switch (wsel) {
        case 0: src = w0; break; case 1: src = w1; break;
        case 2: src = w2; break; case 3: src = w3; break;
        case 4: src = w4; break; case 5: src = w5; break;
        case 6: src = w6; break; default: src = w7; break;
    }
    dw[(size_t)wsel * NW + wi] = pack_f32(src[wi]);
}

__global__ void __launch_bounds__(256) k_proj_all(
    const uint32_t* im, const uint32_t* tx, const uint32_t* w,
    const float* i2t_bq, const float* i2t_bk, const float* i2t_bv,
    const float* t2i_bq, const float* t2i_bk, const float* t2i_bv,
    uint32_t* qi, uint32_t* ki, uint32_t* vi,
    uint32_t* qt, uint32_t* kt, uint32_t* vt)
{
    const int WN = Hd * Hd;
    const int y = blockIdx.y;
    GArgs g;
    g.lda = Hd; g.ldb = Hd; g.ldc = Hd; g.K = Hd; g.alpha = 1.f;
    g.n0 = blockIdx.x * 64; g.rs = nullptr;
    g.tr_ld = 1; g.tr_rows = 1; g.tr_col0 = 0;
    bool om2 = false;
    if (y < 128) {
        g.A = im; g.B = w + 0 * WN; g.bias = i2t_bq; g.C = qi; g.m0 = y * 128;
    } else if (y < 256) {
        g.A = im; g.B = w + 5 * WN; g.bias = t2i_bk; g.C = ki; g.m0 = (y - 128) * 128;
    } else if (y < 384) {
        g.A = im; g.B = w + 6 * WN; g.bias = t2i_bv; g.C = vi; g.m0 = (y - 256) * 128;
        g.tr_ld = SQI; g.tr_rows = SQI; g.tr_col0 = blockIdx.x; om2 = true;
    } else if (y < 448) {
        g.A = tx; g.B = w + 4 * WN; g.bias = t2i_bq; g.C = qt; g.m0 = (y - 384) * 128;
    } else if (y < 512) {
        g.A = tx; g.B = w + 1 * WN; g.bias = i2t_bk; g.C = kt; g.m0 = (y - 448) * 128;
    } else {
        g.A = tx; g.B = w + 2 * WN; g.bias = i2t_bv; g.C = vt; g.m0 = (y - 512) * 128;
        g.tr_ld = SQT; g.tr_rows = SQT; g.tr_col0 = blockIdx.x; om2 = true;
    }
    if (om2) gemm_mma<2, true>(g); else gemm_mma<1, true>(g);
}

__global__ void k_avg_all(const uint32_t* S0, const uint32_t* S1, const float* rsum,
                          float* A0, float* A1)
{
    const int b = blockIdx.y, t = threadIdx.x;
    int q = blockIdx.x;
    const uint32_t* W; const float* rs; float* A; int Sq, Skv;
    if (q < SQI) { W = S0; rs = rsum;            A = A0; Sq = SQI; Skv = SQT; }
    else { q -= SQI; W = S1; rs = rsum + NZ*SQI; A = A1; Sq = SQT; Skv = SQI; }
    const size_t hstride = (size_t)Sq * Skv;
    float inv[4];
#pragma unroll
    for (int h = 0; h < 4; h++) inv[h] = 0.25f / rs[(size_t)(b * 4 + h) * Sq + q];
    const uint32_t* w0 = W + ((size_t)(b * 4) * Sq + q) * (size_t)Skv;
    float* Ar = A + ((size_t)b * Sq + q) * (size_t)Skv;
    for (int k = t; k < Skv; k += 256) {
        float a = 0.f;
#pragma unroll
        for (int h = 0; h < 4; h++)
            a += unpack_f32(w0[(size_t)h * hstride + k]) * inv[h];
        Ar[k] = a;
    }
}

__global__ void __launch_bounds__(256) k_projout_all(
    const uint32_t* ai, const uint32_t* at, const uint32_t* w,
    const float* i2t_bo, const float* t2i_bo, float* oi, float* ot)
{
    const int WN = Hd * Hd;
    const int y = blockIdx.y;
    GArgs g;
    g.lda = Hd; g.ldb = Hd; g.ldc = Hd; g.K = Hd; g.alpha = 1.f;
    g.n0 = blockIdx.x * 64; g.rs = nullptr;
    g.tr_ld = 1; g.tr_rows = 1; g.tr_col0 = 0;
    if (y < 128) { g.A = ai; g.B = w + 3 * WN; g.bias = i2t_bo; g.C = oi; g.m0 = y * 128; }
    else         { g.A = at; g.B = w + 7 * WN; g.bias = t2i_bo; g.C = ot; g.m0 = (y - 128) * 128; }
    gemm_mma<0, true>(g);
}

__global__ void k_reluln_all(const float* oi, const float* ot,
                             const float* g0, const float* b0f,
                             const float* g1, const float* b1f,
                             float* out0, float* out1)
{
    __shared__ float s1[256], s2[256];
    int row = blockIdx.x;
    const int t = threadIdx.x;
    const float* O; const float* gamma; const float* beta; float* out;
    if (row < RI) { O = oi; gamma = g0; beta = b0f; out = out0; }
    else { row -= RI; O = ot; gamma = g1; beta = b1f; out = out1; }
    float x = O[(size_t)row * Hd + t];
    x = fmaxf(x, 0.f);
    s1[t] = x; s2[t] = x * x;
    __syncthreads();
    for (int s = 128; s > 0; s >>= 1) {
        if (t < s) { s1[t] += s1[t + s]; s2[t] += s2[t + s]; }
        __syncthreads();
    }
    const float mean = s1[0] * (1.f / Hd);
    const float var = s2[0] * (1.f / Hd) - mean * mean;
    const float rstd = rsqrtf(var + 1e-5f);
    out[(size_t)row * Hd + t] = (x - mean) * rstd * gamma[t] + beta[t];
}

// ---------------- launch ----------------
extern "C" void kernel_launch(void* const* d_in, const int* in_sizes, int n_in,
                              void* d_out, int out_size) {
    const float* image  = (const float*)d_in[0];
    const float* text   = (const float*)d_in[1];
    const float* i2t_wq = (const float*)d_in[2];
    const float* i2t_bq = (const float*)d_in[3];
    const float* i2t_wk = (const float*)d_in[4];
    const float* i2t_bk = (const float*)d_in[5];
    const float* i2t_wv = (const float*)d_in[6];
    const float* i2t_bv = (const float*)d_in[7];
    const float* i2t_wo = (const float*)d_in[8];
    const float* i2t_bo = (const float*)d_in[9];
    const float* i2t_g  = (const float*)d_in[10];
    const float* i2t_be = (const float*)d_in[11];
    const float* t2i_wq = (const float*)d_in[12];
    const float* t2i_bq = (const float*)d_in[13];
    const float* t2i_wk = (const float*)d_in[14];
    const float* t2i_bk = (const float*)d_in[15];
    const float* t2i_wv = (const float*)d_in[16];
    const float* t2i_bv = (const float*)d_in[17];
    const float* t2i_wo = (const float*)d_in[18];
    const float* t2i_bo = (const float*)d_in[19];
    const float* t2i_g  = (const float*)d_in[20];
    const float* t2i_be = (const float*)d_in[21];

    float* out = (float*)d_out;
    float* out_i2t_feat = out;
    float* out_t2i_feat = out + (size_t)RI * Hd;
    float* out_i2t_A    = out_t2i_feat + (size_t)RT * Hd;
    float* out_t2i_A    = out_i2t_A + (size_t)BAT * SQI * SQT;

    float *im, *tx, *w, *qi, *ki, *vi, *qt, *kt, *vt, *ai, *at, *oi, *ot;
    float *S0, *S1, *rsum;
    cudaGetSymbolAddress((void**)&im, g_im);
    cudaGetSymbolAddress((void**)&tx, g_tx);
    cudaGetSymbolAddress((void**)&w,  g_w);
    cudaGetSymbolAddress((void**)&qi, g_qi);
    cudaGetSymbolAddress((void**)&ki, g_ki);
    cudaGetSymbolAddress((void**)&vi, g_vi);
    cudaGetSymbolAddress((void**)&qt, g_qt);
    cudaGetSymbolAddress((void**)&kt, g_kt);
    cudaGetSymbolAddress((void**)&vt, g_vt);
    cudaGetSymbolAddress((void**)&ai, g_ai);
    cudaGetSymbolAddress((void**)&at, g_at);
    cudaGetSymbolAddress((void**)&oi, g_oi);
    cudaGetSymbolAddress((void**)&ot, g_ot);
    cudaGetSymbolAddress((void**)&S0, g_S0);
    cudaGetSymbolAddress((void**)&S1, g_S1);
    cudaGetSymbolAddress((void**)&rsum, g_rsum);

    cudaFuncSetAttribute(k_proj_all,    cudaFuncAttributeMaxDynamicSharedMemorySize, SMEM_GEMM);
    cudaFuncSetAttribute(k_attn_all,    cudaFuncAttributeMaxDynamicSharedMemorySize, SMEM_ATT);
    cudaFuncSetAttribute(k_projout_all, cudaFuncAttributeMaxDynamicSharedMemorySize, SMEM_GEMM);

    const dim3 blk(256);
    const int NPACK = RI * Hd + RT * Hd + 8 * Hd * Hd;

    k_pack_all<<<(NPACK + 255) / 256, blk>>>(
        image, text, i2t_wq, i2t_wk, i2t_wv, i2t_wo, t2i_wq, t2i_wk, t2i_wv, t2i_wo,
        (uint32_t*)im, (uint32_t*)tx, (uint32_t*)w);

    k_proj_all<<<dim3(4, 576), blk, SMEM_GEMM>>>(
        (uint32_t*)im, (uint32_t*)tx, (uint32_t*)w,
        i2t_bq, i2t_bk, i2t_bv, t2i_bq, t2i_bk, t2i_bv,
        (uint32_t*)qi, (uint32_t*)ki, (uint32_t*)vi,
        (uint32_t*)qt, (uint32_t*)kt, (uint32_t*)vt);

    // fused scores+exp+rowsum+PV: t2i occupies x<8 (longer blocks first), i2t x 8..23
    k_attn_all<<<dim3(24, 32), blk, SMEM_ATT>>>(
        (uint32_t*)qi, (uint32_t*)kt, (uint32_t*)qt, (uint32_t*)ki,
        (uint32_t*)vt, (uint32_t*)vi,
        (uint32_t*)S0, (uint32_t*)S1, rsum, (uint32_t*)ai, (uint32_t*)at);

    k_avg_all<<<dim3(SQI + SQT, BAT), blk>>>(
        (uint32_t*)S0, (uint32_t*)S1, rsum, out_i2t_A, out_t2i_A);

    k_projout_all<<<dim3(4, 192), blk, SMEM_GEMM>>>(
        (uint32_t*)ai, (uint32_t*)at, (uint32_t*)w, i2t_bo, t2i_bo, oi, ot);

    k_reluln_all<<<RI + RT, blk>>>(oi, ot, i2t_g, i2t_be, t2i_g, t2i_be,
                                   out_i2t_feat, out_t2i_feat);
}